// round 11
// baseline (speedup 1.0000x reference)
#include <cuda_runtime.h>
#include <cstdint>

// Flag: 1 if idx buffer is int64, 0 if int32.
__device__ int g_idx_is64;

// Detect idx dtype: for int64 indices in [0, 1e6) the high words are all 0;
// for random int32 indices the odd words are ~never all zero across 64 entries.
__global__ void detect_idx_kernel(const unsigned int* __restrict__ idx_words) {
    int is64 = 1;
    #pragma unroll 1
    for (int k = 0; k < 64; ++k) {
        if (idx_words[2 * k + 1] != 0u) { is64 = 0; break; }
    }
    g_idx_is64 = is64;
}

// L2 access policy: evict_last (keep the 64MB values table resident in L2).
__device__ __forceinline__ unsigned long long make_evict_last_policy() {
    unsigned long long pol;
    asm volatile("createpolicy.fractional.L2::evict_last.b64 %0, 1.0;" : "=l"(pol));
    return pol;
}

// Scalar gather load, L2-resident via cache-hint policy (R6 winner shape:
// 16 lanes of one LDG cover one contiguous 64B row).
__device__ __forceinline__ float ldg_L2_resident(const float* p, unsigned long long pol) {
    float v;
    asm volatile("ld.global.nc.L2::cache_hint.f32 %0, [%1], %2;"
                 : "=f"(v) : "l"(p), "l"(pol));
    return v;
}

// Load the 8 fan-in indices of neuron n into int regs (indices < 2^20).
__device__ __forceinline__ void load_idx(const void* idx_raw, int is64, int n, int rows[8]) {
    if (is64) {
        const int4* p = (const int4*)((const long long*)idx_raw + (long long)n * 8);
        int4 q0 = p[0], q1 = p[1], q2 = p[2], q3 = p[3];
        rows[0] = q0.x; rows[1] = q0.z;   // low words of each int64
        rows[2] = q1.x; rows[3] = q1.z;
        rows[4] = q2.x; rows[5] = q2.z;
        rows[6] = q3.x; rows[7] = q3.z;
    } else {
        const int4* p = (const int4*)((const int*)idx_raw + n * 8);
        int4 q0 = p[0], q1 = p[1];
        rows[0] = q0.x; rows[1] = q0.y; rows[2] = q0.z; rows[3] = q0.w;
        rows[4] = q1.x; rows[5] = q1.y; rows[6] = q1.z; rows[7] = q1.w;
    }
}

// Persistent kernel: each 16-lane group processes neurons n, n+stride, ...
// with the NEXT iteration's idx prefetched at the top of the current one,
// removing the ~600-cycle idx load from the per-iteration critical path.
// Within an iteration (R6 structure):
//   s[d] = sum_k values[idx[n,k]*16 + d]   (coalesced 64B gathers, L2-pinned)
//   y[d] = b[n,d] + sum_j W[n,d,j] * s[j]  (s[j] via shfl width 16)
//   out  = tanh(y)
__global__ __launch_bounds__(256)
void weighted_atom_kernel(const float* __restrict__ values,
                          const void*  __restrict__ idx_raw,
                          const float* __restrict__ W,
                          const float* __restrict__ bvec,
                          float* __restrict__ out,
                          int N)
{
    const int lane   = threadIdx.x & 15;
    const int group  = (blockIdx.x * blockDim.x + threadIdx.x) >> 4;
    const int stride = (gridDim.x * blockDim.x) >> 4;   // total 16-lane groups
    const int is64   = g_idx_is64;

    const unsigned long long pol = make_evict_last_policy();
    const unsigned mask = 0xFFFFFFFFu;

    int n = group;
    if (n >= N) return;

    int rows[8];
    load_idx(idx_raw, is64, n, rows);      // prologue: first iteration's idx

    #pragma unroll 1
    for (; n < N; ) {
        const int n_next = n + stride;

        // ---- prefetch next iteration's idx (latency hidden under this iter) ----
        int rows_next[8];
        if (n_next < N) load_idx(idx_raw, is64, n_next, rows_next);

        // ---- gather + fan-in sum: lane d owns element d; L2-resident ----
        float s = 0.0f;
        #pragma unroll
        for (int k = 0; k < 8; ++k)
            s += ldg_L2_resident(values + (size_t)rows[k] * 16 + lane, pol);

        // ---- streaming W (4 x LDG.128, evict-first) + b ----
        const float4* Wrow4 = (const float4*)(W + (size_t)n * 256 + (size_t)lane * 16);
        float4 w0 = __ldcs(Wrow4 + 0);
        float4 w1 = __ldcs(Wrow4 + 1);
        float4 w2 = __ldcs(Wrow4 + 2);
        float4 w3 = __ldcs(Wrow4 + 3);
        float  y  = __ldcs(bvec + n * 16 + lane);

        y += w0.x * __shfl_sync(mask, s,  0, 16);
        y += w0.y * __shfl_sync(mask, s,  1, 16);
        y += w0.z * __shfl_sync(mask, s,  2, 16);
        y += w0.w * __shfl_sync(mask, s,  3, 16);
        y += w1.x * __shfl_sync(mask, s,  4, 16);
        y += w1.y * __shfl_sync(mask, s,  5, 16);
        y += w1.z * __shfl_sync(mask, s,  6, 16);
        y += w1.w * __shfl_sync(mask, s,  7, 16);
        y += w2.x * __shfl_sync(mask, s,  8, 16);
        y += w2.y * __shfl_sync(mask, s,  9, 16);
        y += w2.z * __shfl_sync(mask, s, 10, 16);
        y += w2.w * __shfl_sync(mask, s, 11, 16);
        y += w3.x * __shfl_sync(mask, s, 12, 16);
        y += w3.y * __shfl_sync(mask, s, 13, 16);
        y += w3.z * __shfl_sync(mask, s, 14, 16);
        y += w3.w * __shfl_sync(mask, s, 15, 16);

        __stcs(out + n * 16 + lane, tanhf(y));

        n = n_next;
        #pragma unroll
        for (int k = 0; k < 8; ++k) rows[k] = rows_next[k];
    }
}

extern "C" void kernel_launch(void* const* d_in, const int* in_sizes, int n_in,
                              void* d_out, int out_size)
{
    // metadata order == setup_inputs order: values, idx, W, b
    const float* values = (const float*)d_in[0];
    const void*  idx    = d_in[1];
    const float* W      = (const float*)d_in[2];
    const float* bvec   = (const float*)d_in[3];
    float* out          = (float*)d_out;

    const int N = in_sizes[3] / 16;   // b has N*16 elements

    detect_idx_kernel<<<1, 1>>>((const unsigned int*)idx);

    const int threads = 256;           // 16 groups per block
    const int blocks  = 148 * 8;       // one persistent wave across all SMs
    weighted_atom_kernel<<<blocks, threads>>>(values, idx, W, bvec, out, N);
}

// round 12
// speedup vs baseline: 1.2617x; 1.2617x over previous
#include <cuda_runtime.h>
#include <cstdint>

// Flag: 1 if idx buffer is int64, 0 if int32.
__device__ int g_idx_is64;

// Detect idx dtype: for int64 indices in [0, 1e6) the high words are all 0;
// for random int32 indices the odd words are ~never all zero across 64 entries.
__global__ void detect_idx_kernel(const unsigned int* __restrict__ idx_words) {
    int is64 = 1;
    #pragma unroll 1
    for (int k = 0; k < 64; ++k) {
        if (idx_words[2 * k + 1] != 0u) { is64 = 0; break; }
    }
    g_idx_is64 = is64;
}

// L2 policies: evict_last pins the 64MB values table in L2;
// evict_first marks the 512MB W stream as use-once.
__device__ __forceinline__ unsigned long long make_evict_last_policy() {
    unsigned long long pol;
    asm volatile("createpolicy.fractional.L2::evict_last.b64 %0, 1.0;" : "=l"(pol));
    return pol;
}
__device__ __forceinline__ unsigned long long make_evict_first_policy() {
    unsigned long long pol;
    asm volatile("createpolicy.fractional.L2::evict_first.b64 %0, 1.0;" : "=l"(pol));
    return pol;
}

// Gather load: L2-resident, NO L1 allocation (zero L1 reuse; stop fill churn).
__device__ __forceinline__ float ldg_gather(const float* p, unsigned long long pol) {
    float v;
    asm volatile("ld.global.nc.L1::no_allocate.L2::cache_hint.f32 %0, [%1], %2;"
                 : "=f"(v) : "l"(p), "l"(pol));
    return v;
}

// Streaming 16B load: L2 evict-first, NO L1 allocation (use-once data).
__device__ __forceinline__ float4 ldg4_stream(const float4* p, unsigned long long pol) {
    float4 v;
    asm volatile("ld.global.nc.L1::no_allocate.L2::cache_hint.v4.f32 {%0,%1,%2,%3}, [%4], %5;"
                 : "=f"(v.x), "=f"(v.y), "=f"(v.z), "=f"(v.w)
                 : "l"(p), "l"(pol));
    return v;
}
__device__ __forceinline__ float ldg_stream(const float* p, unsigned long long pol) {
    float v;
    asm volatile("ld.global.nc.L1::no_allocate.L2::cache_hint.f32 %0, [%1], %2;"
                 : "=f"(v) : "l"(p), "l"(pol));
    return v;
}

// One neuron per 16 threads (R6 winning structure, R6 instruction order).
// lane = element index d in [0,16).
//   s[d]  = sum_k values[idx[n,k]*16 + d]   (coalesced 64B gathers, L2-pinned)
//   y[d]  = b[n,d] + sum_j W[n,d,j] * s[j]  (s[j] via shfl width 16)
//   out   = tanh(y)
__global__ __launch_bounds__(256)
void weighted_atom_kernel(const float* __restrict__ values,
                          const void*  __restrict__ idx_raw,
                          const float* __restrict__ W,
                          const float* __restrict__ bvec,
                          float* __restrict__ out,
                          int N)
{
    const int gid  = blockIdx.x * blockDim.x + threadIdx.x;
    const int n    = gid >> 4;
    const int lane = gid & 15;
    if (n >= N) return;   // grid sized exactly; never taken (keeps shfl safe)

    const unsigned long long pol_keep   = make_evict_last_policy();
    const unsigned long long pol_stream = make_evict_first_policy();

    // ---- fetch the 8 fan-in row indices with vector loads (R6 order: first) ----
    long long rows[8];
    if (g_idx_is64) {
        const int4* p = (const int4*)((const long long*)idx_raw + (long long)n * 8);
        int4 q0 = p[0], q1 = p[1], q2 = p[2], q3 = p[3];
        rows[0] = ((long long)q0.y << 32) | (unsigned int)q0.x;
        rows[1] = ((long long)q0.w << 32) | (unsigned int)q0.z;
        rows[2] = ((long long)q1.y << 32) | (unsigned int)q1.x;
        rows[3] = ((long long)q1.w << 32) | (unsigned int)q1.z;
        rows[4] = ((long long)q2.y << 32) | (unsigned int)q2.x;
        rows[5] = ((long long)q2.w << 32) | (unsigned int)q2.z;
        rows[6] = ((long long)q3.y << 32) | (unsigned int)q3.x;
        rows[7] = ((long long)q3.w << 32) | (unsigned int)q3.z;
    } else {
        const int4* p = (const int4*)((const int*)idx_raw + n * 8);
        int4 q0 = p[0], q1 = p[1];
        rows[0] = q0.x; rows[1] = q0.y; rows[2] = q0.z; rows[3] = q0.w;
        rows[4] = q1.x; rows[5] = q1.y; rows[6] = q1.z; rows[7] = q1.w;
    }

    // ---- streaming loads of W (4 x LDG.128) + b: L1-bypass, L2 evict-first ----
    const float4* Wrow4 = (const float4*)(W + (size_t)n * 256 + (size_t)lane * 16);
    float4 w0 = ldg4_stream(Wrow4 + 0, pol_stream);
    float4 w1 = ldg4_stream(Wrow4 + 1, pol_stream);
    float4 w2 = ldg4_stream(Wrow4 + 2, pol_stream);
    float4 w3 = ldg4_stream(Wrow4 + 3, pol_stream);
    float  y  = ldg_stream(bvec + gid, pol_stream);   // b[n*16 + lane]

    // ---- gather + fan-in sum: lane d owns element d; L2-resident, L1-bypass ----
    float s = 0.0f;
    #pragma unroll
    for (int k = 0; k < 8; ++k) {
        s += ldg_gather(values + rows[k] * 16 + lane, pol_keep);
    }

    const unsigned mask = 0xFFFFFFFFu;
    y += w0.x * __shfl_sync(mask, s,  0, 16);
    y += w0.y * __shfl_sync(mask, s,  1, 16);
    y += w0.z * __shfl_sync(mask, s,  2, 16);
    y += w0.w * __shfl_sync(mask, s,  3, 16);
    y += w1.x * __shfl_sync(mask, s,  4, 16);
    y += w1.y * __shfl_sync(mask, s,  5, 16);
    y += w1.z * __shfl_sync(mask, s,  6, 16);
    y += w1.w * __shfl_sync(mask, s,  7, 16);
    y += w2.x * __shfl_sync(mask, s,  8, 16);
    y += w2.y * __shfl_sync(mask, s,  9, 16);
    y += w2.z * __shfl_sync(mask, s, 10, 16);
    y += w2.w * __shfl_sync(mask, s, 11, 16);
    y += w3.x * __shfl_sync(mask, s, 12, 16);
    y += w3.y * __shfl_sync(mask, s, 13, 16);
    y += w3.z * __shfl_sync(mask, s, 14, 16);
    y += w3.w * __shfl_sync(mask, s, 15, 16);

    __stcs(out + gid, tanhf(y));
}

extern "C" void kernel_launch(void* const* d_in, const int* in_sizes, int n_in,
                              void* d_out, int out_size)
{
    // metadata order == setup_inputs order: values, idx, W, b
    const float* values = (const float*)d_in[0];
    const void*  idx    = d_in[1];
    const float* W      = (const float*)d_in[2];
    const float* bvec   = (const float*)d_in[3];
    float* out          = (float*)d_out;

    const int N = in_sizes[3] / 16;   // b has N*16 elements

    detect_idx_kernel<<<1, 1>>>((const unsigned int*)idx);

    const int threads = 256;
    const int total   = N * 16;
    const int blocks  = (total + threads - 1) / threads;
    weighted_atom_kernel<<<blocks, threads>>>(values, idx, W, bvec, out, N);
}

// round 13
// speedup vs baseline: 1.2621x; 1.0003x over previous
#include <cuda_runtime.h>
#include <cstdint>

// Flag: 1 if idx buffer is int64, 0 if int32.
__device__ int g_idx_is64;

// Parallel dtype detect: 64 threads each check one high word; ballot-reduce.
// For int64 indices in [0,1e6) every high word is 0; for random int32 the
// "high words" are themselves random indices (~never all zero across 64).
// Worst case ~1us (vs ~20us for a serial dependent-load loop if idx is int64).
__global__ void detect_idx_kernel(const unsigned int* __restrict__ idx_words) {
    const int t = threadIdx.x;                 // 64 threads
    unsigned int w = idx_words[2 * t + 1];     // high word of entry t
    unsigned nz_lo = __ballot_sync(0xFFFFFFFFu, (t < 32) && (w != 0u));
    unsigned nz_hi = __ballot_sync(0xFFFFFFFFu, (t >= 32) && (w != 0u));
    if (t == 0) g_idx_is64 = ((nz_lo | nz_hi) == 0u) ? 1 : 0;
}

// L2 access policy: evict_last (keep the 64MB values table resident in L2
// against the 512MB streaming W read).
__device__ __forceinline__ unsigned long long make_evict_last_policy() {
    unsigned long long pol;
    asm volatile("createpolicy.fractional.L2::evict_last.b64 %0, 1.0;" : "=l"(pol));
    return pol;
}

// Scalar gather load, L2-resident via cache-hint policy. R6 winner shape:
// the 16 lanes of one LDG cover one contiguous 64B values row (1 wavefront).
__device__ __forceinline__ float ldg_L2_resident(const float* p, unsigned long long pol) {
    float v;
    asm volatile("ld.global.nc.L2::cache_hint.f32 %0, [%1], %2;"
                 : "=f"(v) : "l"(p), "l"(pol));
    return v;
}

// One neuron per 16 threads. lane = element index d in [0,16).
//   s[d]  = sum_k values[idx[n,k]*16 + d]   (coalesced 64B gathers, L2-pinned)
//   y[d]  = b[n,d] + sum_j W[n,d,j] * s[j]  (s[j] via shfl width 16)
//   out   = tanh(y)
__global__ __launch_bounds__(256)
void weighted_atom_kernel(const float* __restrict__ values,
                          const void*  __restrict__ idx_raw,
                          const float* __restrict__ W,
                          const float* __restrict__ bvec,
                          float* __restrict__ out,
                          int N)
{
    const int gid  = blockIdx.x * blockDim.x + threadIdx.x;
    const int n    = gid >> 4;
    const int lane = gid & 15;
    if (n >= N) return;   // grid sized exactly; never taken (keeps shfl safe)

    const unsigned long long pol = make_evict_last_policy();

    // ---- fetch the 8 fan-in row indices with vector loads ----
    long long rows[8];
    if (g_idx_is64) {
        // 8 x int64 = 64B = 4 x int4 (uniform across the 16-lane group)
        const int4* p = (const int4*)((const long long*)idx_raw + (long long)n * 8);
        int4 q0 = p[0], q1 = p[1], q2 = p[2], q3 = p[3];
        rows[0] = ((long long)q0.y << 32) | (unsigned int)q0.x;
        rows[1] = ((long long)q0.w << 32) | (unsigned int)q0.z;
        rows[2] = ((long long)q1.y << 32) | (unsigned int)q1.x;
        rows[3] = ((long long)q1.w << 32) | (unsigned int)q1.z;
        rows[4] = ((long long)q2.y << 32) | (unsigned int)q2.x;
        rows[5] = ((long long)q2.w << 32) | (unsigned int)q2.z;
        rows[6] = ((long long)q3.y << 32) | (unsigned int)q3.x;
        rows[7] = ((long long)q3.w << 32) | (unsigned int)q3.z;
    } else {
        // 8 x int32 = 32B = 2 x int4
        const int4* p = (const int4*)((const int*)idx_raw + n * 8);
        int4 q0 = p[0], q1 = p[1];
        rows[0] = q0.x; rows[1] = q0.y; rows[2] = q0.z; rows[3] = q0.w;
        rows[4] = q1.x; rows[5] = q1.y; rows[6] = q1.z; rows[7] = q1.w;
    }

    // ---- streaming loads of W (4 x LDG.128, evict-first) + b ----
    const float4* Wrow4 = (const float4*)(W + (size_t)n * 256 + (size_t)lane * 16);
    float4 w0 = __ldcs(Wrow4 + 0);
    float4 w1 = __ldcs(Wrow4 + 1);
    float4 w2 = __ldcs(Wrow4 + 2);
    float4 w3 = __ldcs(Wrow4 + 3);
    float  y  = __ldcs(bvec + gid);   // b[n*16 + lane]

    // ---- gather + fan-in sum: lane d owns element d; L2-resident ----
    // Two partial sums halve the dependent-FADD tail after the loads land.
    float sa = 0.0f, sb = 0.0f;
    #pragma unroll
    for (int k = 0; k < 4; ++k) {
        sa += ldg_L2_resident(values + rows[2 * k]     * 16 + lane, pol);
        sb += ldg_L2_resident(values + rows[2 * k + 1] * 16 + lane, pol);
    }
    const float s = sa + sb;

    const unsigned mask = 0xFFFFFFFFu;
    y += w0.x * __shfl_sync(mask, s,  0, 16);
    y += w0.y * __shfl_sync(mask, s,  1, 16);
    y += w0.z * __shfl_sync(mask, s,  2, 16);
    y += w0.w * __shfl_sync(mask, s,  3, 16);
    y += w1.x * __shfl_sync(mask, s,  4, 16);
    y += w1.y * __shfl_sync(mask, s,  5, 16);
    y += w1.z * __shfl_sync(mask, s,  6, 16);
    y += w1.w * __shfl_sync(mask, s,  7, 16);
    y += w2.x * __shfl_sync(mask, s,  8, 16);
    y += w2.y * __shfl_sync(mask, s,  9, 16);
    y += w2.z * __shfl_sync(mask, s, 10, 16);
    y += w2.w * __shfl_sync(mask, s, 11, 16);
    y += w3.x * __shfl_sync(mask, s, 12, 16);
    y += w3.y * __shfl_sync(mask, s, 13, 16);
    y += w3.z * __shfl_sync(mask, s, 14, 16);
    y += w3.w * __shfl_sync(mask, s, 15, 16);

    __stcs(out + gid, tanhf(y));
}

extern "C" void kernel_launch(void* const* d_in, const int* in_sizes, int n_in,
                              void* d_out, int out_size)
{
    // metadata order == setup_inputs order: values, idx, W, b
    const float* values = (const float*)d_in[0];
    const void*  idx    = d_in[1];
    const float* W      = (const float*)d_in[2];
    const float* bvec   = (const float*)d_in[3];
    float* out          = (float*)d_out;

    const int N = in_sizes[3] / 16;   // b has N*16 elements

    detect_idx_kernel<<<1, 64>>>((const unsigned int*)idx);

    const int threads = 256;
    const int total   = N * 16;
    const int blocks  = (total + threads - 1) / threads;
    weighted_atom_kernel<<<blocks, threads>>>(values, idx, W, bvec, out, N);
}

// round 14
// speedup vs baseline: 1.2832x; 1.0167x over previous
#include <cuda_runtime.h>
#include <cstdint>

// L2 access policy: evict_last (keep the 64MB values table resident in L2
// against the 512MB streaming W read).
__device__ __forceinline__ unsigned long long make_evict_last_policy() {
    unsigned long long pol;
    asm volatile("createpolicy.fractional.L2::evict_last.b64 %0, 1.0;" : "=l"(pol));
    return pol;
}

// Scalar gather load, L2-resident via cache-hint policy. R6 winner shape:
// the 16 lanes of one LDG cover one contiguous 64B values row (1 wavefront).
__device__ __forceinline__ float ldg_L2_resident(const float* p, unsigned long long pol) {
    float v;
    asm volatile("ld.global.nc.L2::cache_hint.f32 %0, [%1], %2;"
                 : "=f"(v) : "l"(p), "l"(pol));
    return v;
}

// One neuron per 16 threads. lane = element index d in [0,16).
//   s[d]  = sum_k values[idx[n,k]*16 + d]   (coalesced 64B gathers, L2-pinned)
//   y[d]  = b[n,d] + sum_j W[n,d,j] * s[j]  (s[j] via shfl width 16)
//   out   = tanh(y)
// idx dtype (int32 vs int64) detected inline from the first 32 bytes of idx:
// two uniform-address __ldg loads (broadcast; ~free after first touch/SM).
// For int64 indices in [0,1e6) the odd 32-bit words are all 0; for random
// int32 indices, 4 odd words all zero has probability ~(1e-6)^4 = 1e-24.
__global__ __launch_bounds__(256)
void weighted_atom_kernel(const float* __restrict__ values,
                          const void*  __restrict__ idx_raw,
                          const float* __restrict__ W,
                          const float* __restrict__ bvec,
                          float* __restrict__ out,
                          int N)
{
    const int gid  = blockIdx.x * blockDim.x + threadIdx.x;
    const int n    = gid >> 4;
    const int lane = gid & 15;
    if (n >= N) return;   // grid sized exactly; never taken (keeps shfl safe)

    const unsigned long long pol = make_evict_last_policy();

    // ---- inline dtype detect (uniform loads, grid-wide same address) ----
    const int4* head = (const int4*)idx_raw;
    int4 h0 = __ldg(head + 0);
    int4 h1 = __ldg(head + 1);
    const bool is64 = ((h0.y | h0.w | h1.y | h1.w) == 0);

    // ---- fetch the 8 fan-in row indices with vector loads ----
    long long rows[8];
    if (is64) {
        // 8 x int64 = 64B = 4 x int4 (uniform across the 16-lane group)
        const int4* p = (const int4*)((const long long*)idx_raw + (long long)n * 8);
        int4 q0 = p[0], q1 = p[1], q2 = p[2], q3 = p[3];
        rows[0] = ((long long)q0.y << 32) | (unsigned int)q0.x;
        rows[1] = ((long long)q0.w << 32) | (unsigned int)q0.z;
        rows[2] = ((long long)q1.y << 32) | (unsigned int)q1.x;
        rows[3] = ((long long)q1.w << 32) | (unsigned int)q1.z;
        rows[4] = ((long long)q2.y << 32) | (unsigned int)q2.x;
        rows[5] = ((long long)q2.w << 32) | (unsigned int)q2.z;
        rows[6] = ((long long)q3.y << 32) | (unsigned int)q3.x;
        rows[7] = ((long long)q3.w << 32) | (unsigned int)q3.z;
    } else {
        // 8 x int32 = 32B = 2 x int4
        const int4* p = (const int4*)((const int*)idx_raw + n * 8);
        int4 q0 = p[0], q1 = p[1];
        rows[0] = q0.x; rows[1] = q0.y; rows[2] = q0.z; rows[3] = q0.w;
        rows[4] = q1.x; rows[5] = q1.y; rows[6] = q1.z; rows[7] = q1.w;
    }

    // ---- streaming loads of W (4 x LDG.128, evict-first) + b ----
    const float4* Wrow4 = (const float4*)(W + (size_t)n * 256 + (size_t)lane * 16);
    float4 w0 = __ldcs(Wrow4 + 0);
    float4 w1 = __ldcs(Wrow4 + 1);
    float4 w2 = __ldcs(Wrow4 + 2);
    float4 w3 = __ldcs(Wrow4 + 3);
    float  y  = __ldcs(bvec + gid);   // b[n*16 + lane]

    // ---- gather + fan-in sum: lane d owns element d; L2-resident ----
    float s = 0.0f;
    #pragma unroll
    for (int k = 0; k < 8; ++k) {
        s += ldg_L2_resident(values + rows[k] * 16 + lane, pol);
    }

    const unsigned mask = 0xFFFFFFFFu;
    y += w0.x * __shfl_sync(mask, s,  0, 16);
    y += w0.y * __shfl_sync(mask, s,  1, 16);
    y += w0.z * __shfl_sync(mask, s,  2, 16);
    y += w0.w * __shfl_sync(mask, s,  3, 16);
    y += w1.x * __shfl_sync(mask, s,  4, 16);
    y += w1.y * __shfl_sync(mask, s,  5, 16);
    y += w1.z * __shfl_sync(mask, s,  6, 16);
    y += w1.w * __shfl_sync(mask, s,  7, 16);
    y += w2.x * __shfl_sync(mask, s,  8, 16);
    y += w2.y * __shfl_sync(mask, s,  9, 16);
    y += w2.z * __shfl_sync(mask, s, 10, 16);
    y += w2.w * __shfl_sync(mask, s, 11, 16);
    y += w3.x * __shfl_sync(mask, s, 12, 16);
    y += w3.y * __shfl_sync(mask, s, 13, 16);
    y += w3.z * __shfl_sync(mask, s, 14, 16);
    y += w3.w * __shfl_sync(mask, s, 15, 16);

    __stcs(out + gid, tanhf(y));
}

extern "C" void kernel_launch(void* const* d_in, const int* in_sizes, int n_in,
                              void* d_out, int out_size)
{
    // metadata order == setup_inputs order: values, idx, W, b
    const float* values = (const float*)d_in[0];
    const void*  idx    = d_in[1];
    const float* W      = (const float*)d_in[2];
    const float* bvec   = (const float*)d_in[3];
    float* out          = (float*)d_out;

    const int N = in_sizes[3] / 16;   // b has N*16 elements

    const int threads = 256;
    const int total   = N * 16;
    const int blocks  = (total + threads - 1) / threads;
    weighted_atom_kernel<<<blocks, threads>>>(values, idx, W, bvec, out, N);
}